// round 1
// baseline (speedup 1.0000x reference)
#include <cuda_runtime.h>
#include <math.h>

// Problem constants
#define BDIM   32
#define NTRAJ  512
#define LAT    256
#define HID    1024
#define TSTEPS 10
#define NROWS  (NTRAJ + LAT)        // 768 rows of ODE state per batch
#define MTOT   (BDIM * NROWS)       // 24576 total rows

// ---------------- scratch (static device globals; zero-initialized) ----------
__device__ float g_x   [MTOT * LAT];   // ODE state  (25 MB)
__device__ float g_k   [MTOT * LAT];   // last k_i   (25 MB)
__device__ float g_ksum[MTOT * LAT];   // weighted k accumulator (25 MB)
__device__ float g_h   [MTOT * HID];   // hidden activations (100 MB)
__device__ float g_mean[BDIM * LAT];
__device__ float g_cov [BDIM * LAT * LAT];

// ---------------- setup kernels ----------------------------------------------

// copy first_point into state rows [0,512) per batch, and write t=0 output slice
__global__ void k_init(const float* __restrict__ fp, float* __restrict__ out) {
    int i = blockIdx.x * blockDim.x + threadIdx.x;
    if (i >= BDIM * NTRAJ * LAT) return;
    int c = i % LAT;
    int n = (i / LAT) % NTRAJ;
    int b = i / (LAT * NTRAJ);
    float v = fp[i];
    g_x[((size_t)(b * NROWS + n)) * LAT + c] = v;
    out[((((size_t)b * NTRAJ) + n) * TSTEPS + 0) * LAT + c] = v;
}

// per-batch per-latent mean over trajectories
__global__ void k_mean(const float* __restrict__ fp) {
    int b = blockIdx.x;
    int d = threadIdx.x;       // 256 threads
    const float* p = fp + (size_t)b * NTRAJ * LAT + d;
    float s = 0.f;
    for (int n = 0; n < NTRAJ; n++) s += p[(size_t)n * LAT];
    g_mean[b * LAT + d] = s * (1.0f / NTRAJ);
}

// cov[b,d,e] = sum_n (x[b,n,d]-m[b,d]) * (x[b,n,e]-m[b,e])
__global__ void k_cov(const float* __restrict__ fp) {
    int b  = blockIdx.z;
    int d0 = blockIdx.y * 16;
    int e0 = blockIdx.x * 16;
    int ty = threadIdx.y, tx = threadIdx.x;
    __shared__ float Ad[16][17];
    __shared__ float Ae[16][17];
    float md = g_mean[b * LAT + d0 + tx];
    float me = g_mean[b * LAT + e0 + tx];
    const float* base = fp + (size_t)b * NTRAJ * LAT;
    float acc = 0.f;
    for (int n0 = 0; n0 < NTRAJ; n0 += 16) {
        Ad[ty][tx] = base[(size_t)(n0 + ty) * LAT + d0 + tx] - md;
        Ae[ty][tx] = base[(size_t)(n0 + ty) * LAT + e0 + tx] - me;
        __syncthreads();
        #pragma unroll
        for (int k = 0; k < 16; k++)
            acc = fmaf(Ad[k][ty], Ae[k][tx], acc);
        __syncthreads();
    }
    g_cov[((size_t)(b * LAT + d0 + ty)) * LAT + e0 + tx] = acc;
}

// corr = cov / (sd_d * sd_e), written into state rows [512, 768) per batch
__global__ void k_corr() {
    int i = blockIdx.x * blockDim.x + threadIdx.x;
    if (i >= BDIM * LAT * LAT) return;
    int e = i % LAT;
    int d = (i / LAT) % LAT;
    int b = i / (LAT * LAT);
    float c  = g_cov[i];
    float dd = g_cov[((size_t)(b * LAT + d)) * LAT + d];
    float de = g_cov[((size_t)(b * LAT + e)) * LAT + e];
    g_x[((size_t)(b * NROWS + NTRAJ + d)) * LAT + e] = c * rsqrtf(dd * de);
}

// ---------------- GEMM1: H = tanh( (x + cmul*dt*k_prev) @ W1 + b1 ) ----------
// M = 24576, K = 256, N = 1024.  128x128x8 tile, 256 threads, 8x8 per thread.
__global__ __launch_bounds__(256)
void k_gemm1(float cmul, const float* __restrict__ ts, int step,
             const float* __restrict__ W1, const float* __restrict__ b1) {
    __shared__ float As[8][128];
    __shared__ float Bs[8][128];

    float dt = ts[step + 1] - ts[step];
    float cf = cmul * dt;

    int m0 = blockIdx.y * 128;
    int n0 = blockIdx.x * 128;
    int tid = threadIdx.x;
    int tx = tid % 16, ty = tid / 16;

    int arow = tid >> 1;            // 0..127
    int acol = (tid & 1) * 4;       // 0 or 4
    int brow = tid >> 5;            // 0..7
    int bcol = (tid & 31) * 4;      // 0..124

    const float* Aptr = g_x + (size_t)(m0 + arow) * LAT;
    const float* Kptr = g_k + (size_t)(m0 + arow) * LAT;

    float acc[8][8] = {};

    for (int k0 = 0; k0 < LAT; k0 += 8) {
        float4 a = *(const float4*)(Aptr + k0 + acol);
        if (cf != 0.0f) {
            float4 kk = *(const float4*)(Kptr + k0 + acol);
            a.x = fmaf(cf, kk.x, a.x);
            a.y = fmaf(cf, kk.y, a.y);
            a.z = fmaf(cf, kk.z, a.z);
            a.w = fmaf(cf, kk.w, a.w);
        }
        float4 bv = *(const float4*)(W1 + (size_t)(k0 + brow) * HID + n0 + bcol);

        As[acol + 0][arow] = a.x;
        As[acol + 1][arow] = a.y;
        As[acol + 2][arow] = a.z;
        As[acol + 3][arow] = a.w;
        *(float4*)(&Bs[brow][bcol]) = bv;
        __syncthreads();

        #pragma unroll
        for (int kk2 = 0; kk2 < 8; kk2++) {
            float af[8], bf[8];
            #pragma unroll
            for (int i = 0; i < 8; i++) af[i] = As[kk2][ty * 8 + i];
            #pragma unroll
            for (int j = 0; j < 8; j++) bf[j] = Bs[kk2][tx * 8 + j];
            #pragma unroll
            for (int i = 0; i < 8; i++)
                #pragma unroll
                for (int j = 0; j < 8; j++)
                    acc[i][j] = fmaf(af[i], bf[j], acc[i][j]);
        }
        __syncthreads();
    }

    #pragma unroll
    for (int i = 0; i < 8; i++) {
        int row = m0 + ty * 8 + i;
        #pragma unroll
        for (int j = 0; j < 8; j += 4) {
            int col = n0 + tx * 8 + j;
            float4 o;
            o.x = tanhf(acc[i][j + 0] + b1[col + 0]);
            o.y = tanhf(acc[i][j + 1] + b1[col + 1]);
            o.z = tanhf(acc[i][j + 2] + b1[col + 2]);
            o.w = tanhf(acc[i][j + 3] + b1[col + 3]);
            *(float4*)(g_h + (size_t)row * HID + col) = o;
        }
    }
}

// ---------------- GEMM2: Kv = H @ W2, fused RK4 epilogue ----------------------
// M = 24576, K = 1024, N = 256.
// mode 0: ksum = Kv;  k = Kv           (after eval1)
// mode 1: ksum += wgt*Kv;  k = Kv      (after eval2/eval3, wgt = 2)
// mode 2: x += dt/6*(ksum + Kv); write output slice t = step+1  (after eval4)
__global__ __launch_bounds__(256)
void k_gemm2(const float* __restrict__ W2, const float* __restrict__ ts,
             int step, int mode, float wgt, float* __restrict__ out) {
    __shared__ float As[8][128];
    __shared__ float Bs[8][128];

    int m0 = blockIdx.y * 128;
    int n0 = blockIdx.x * 128;
    int tid = threadIdx.x;
    int tx = tid % 16, ty = tid / 16;

    int arow = tid >> 1;
    int acol = (tid & 1) * 4;
    int brow = tid >> 5;
    int bcol = (tid & 31) * 4;

    const float* Aptr = g_h + (size_t)(m0 + arow) * HID;

    float acc[8][8] = {};

    for (int k0 = 0; k0 < HID; k0 += 8) {
        float4 a  = *(const float4*)(Aptr + k0 + acol);
        float4 bv = *(const float4*)(W2 + (size_t)(k0 + brow) * LAT + n0 + bcol);

        As[acol + 0][arow] = a.x;
        As[acol + 1][arow] = a.y;
        As[acol + 2][arow] = a.z;
        As[acol + 3][arow] = a.w;
        *(float4*)(&Bs[brow][bcol]) = bv;
        __syncthreads();

        #pragma unroll
        for (int kk2 = 0; kk2 < 8; kk2++) {
            float af[8], bf[8];
            #pragma unroll
            for (int i = 0; i < 8; i++) af[i] = As[kk2][ty * 8 + i];
            #pragma unroll
            for (int j = 0; j < 8; j++) bf[j] = Bs[kk2][tx * 8 + j];
            #pragma unroll
            for (int i = 0; i < 8; i++)
                #pragma unroll
                for (int j = 0; j < 8; j++)
                    acc[i][j] = fmaf(af[i], bf[j], acc[i][j]);
        }
        __syncthreads();
    }

    float dt = ts[step + 1] - ts[step];
    float s6 = dt / 6.0f;

    #pragma unroll
    for (int i = 0; i < 8; i++) {
        int row = m0 + ty * 8 + i;
        int b = row / NROWS;
        int n = row % NROWS;
        size_t base = (size_t)row * LAT + n0 + tx * 8;
        #pragma unroll
        for (int j = 0; j < 8; j++) {
            float v = acc[i][j];
            size_t idx = base + j;
            if (mode == 0) {
                g_ksum[idx] = v;
                g_k[idx] = v;
            } else if (mode == 1) {
                g_ksum[idx] += wgt * v;
                g_k[idx] = v;
            } else {
                float xn = g_x[idx] + s6 * (g_ksum[idx] + v);
                g_x[idx] = xn;
                if (n < NTRAJ) {
                    out[((((size_t)b * NTRAJ) + n) * TSTEPS + (step + 1)) * LAT
                        + (n0 + tx * 8 + j)] = xn;
                }
            }
        }
    }
}

// ---------------- launch ------------------------------------------------------
extern "C" void kernel_launch(void* const* d_in, const int* in_sizes, int n_in,
                              void* d_out, int out_size) {
    const float* fp = (const float*)d_in[0];   // first_point (32,512,256)
    const float* ts = (const float*)d_in[1];   // time steps (10)
    const float* W1 = (const float*)d_in[2];   // (256,1024)
    const float* b1 = (const float*)d_in[3];   // (1024)
    const float* W2 = (const float*)d_in[4];   // (1024,256)
    float* out = (float*)d_out;                // (32,512,10,256)

    // setup: state init + t=0 output + corrcoef block
    k_init<<<(BDIM * NTRAJ * LAT + 255) / 256, 256>>>(fp, out);
    k_mean<<<BDIM, LAT>>>(fp);
    k_cov<<<dim3(LAT / 16, LAT / 16, BDIM), dim3(16, 16)>>>(fp);
    k_corr<<<(BDIM * LAT * LAT + 255) / 256, 256>>>();

    dim3 g1(HID / 128, MTOT / 128);   // (8, 192)
    dim3 g2(LAT / 128, MTOT / 128);   // (2, 192)

    for (int s = 0; s < TSTEPS - 1; s++) {
        // eval 1: input x
        k_gemm1<<<g1, 256>>>(0.0f, ts, s, W1, b1);
        k_gemm2<<<g2, 256>>>(W2, ts, s, 0, 1.0f, out);
        // eval 2: input x + 0.5*dt*k1
        k_gemm1<<<g1, 256>>>(0.5f, ts, s, W1, b1);
        k_gemm2<<<g2, 256>>>(W2, ts, s, 1, 2.0f, out);
        // eval 3: input x + 0.5*dt*k2
        k_gemm1<<<g1, 256>>>(0.5f, ts, s, W1, b1);
        k_gemm2<<<g2, 256>>>(W2, ts, s, 1, 2.0f, out);
        // eval 4: input x + dt*k3; finalize step
        k_gemm1<<<g1, 256>>>(1.0f, ts, s, W1, b1);
        k_gemm2<<<g2, 256>>>(W2, ts, s, 2, 1.0f, out);
    }
}

// round 2
// speedup vs baseline: 3.0080x; 3.0080x over previous
#include <cuda_runtime.h>
#include <math.h>
#include <stdint.h>

// Problem constants
#define BDIM   32
#define NTRAJ  512
#define LAT    256
#define HID    1024
#define TSTEPS 10
#define NROWS  (NTRAJ + LAT)        // 768 rows of ODE state per batch
#define MTOT   (BDIM * NROWS)       // 24576 total rows

// ---------------- scratch (static device globals) ----------------------------
__device__ float g_x   [MTOT * LAT];   // ODE state
__device__ float g_k   [MTOT * LAT];   // last k_i
__device__ float g_ksum[MTOT * LAT];   // weighted k accumulator
__device__ float g_h   [MTOT * HID];   // hidden activations
__device__ float g_mean[BDIM * LAT];
__device__ float g_cov [BDIM * LAT * LAT];

// ---------------- helpers -----------------------------------------------------
__device__ __forceinline__ float to_tf32(float x) {
    uint32_t u;
    asm("cvt.rna.tf32.f32 %0, %1;" : "=r"(u) : "f"(x));
    return __uint_as_float(u);
}

__device__ __forceinline__ float tanh_fast(float x) {
    float y;
    asm("tanh.approx.f32 %0, %1;" : "=f"(y) : "f"(x));
    return y;
}

__device__ __forceinline__ void mma_tf32(float* d, const uint32_t* a, const uint32_t* b) {
    asm("mma.sync.aligned.m16n8k8.row.col.f32.tf32.tf32.f32 "
        "{%0,%1,%2,%3},{%4,%5,%6,%7},{%8,%9},{%0,%1,%2,%3};"
        : "+f"(d[0]), "+f"(d[1]), "+f"(d[2]), "+f"(d[3])
        : "r"(a[0]), "r"(a[1]), "r"(a[2]), "r"(a[3]), "r"(b[0]), "r"(b[1]));
}

// ---------------- setup kernels ----------------------------------------------
__global__ void k_init(const float* __restrict__ fp, float* __restrict__ out) {
    int i = blockIdx.x * blockDim.x + threadIdx.x;
    if (i >= BDIM * NTRAJ * LAT) return;
    int c = i % LAT;
    int n = (i / LAT) % NTRAJ;
    int b = i / (LAT * NTRAJ);
    float v = fp[i];
    g_x[((size_t)(b * NROWS + n)) * LAT + c] = v;
    out[((((size_t)b * NTRAJ) + n) * TSTEPS + 0) * LAT + c] = v;
}

__global__ void k_mean(const float* __restrict__ fp) {
    int b = blockIdx.x;
    int d = threadIdx.x;
    const float* p = fp + (size_t)b * NTRAJ * LAT + d;
    float s = 0.f;
    for (int n = 0; n < NTRAJ; n++) s += p[(size_t)n * LAT];
    g_mean[b * LAT + d] = s * (1.0f / NTRAJ);
}

__global__ void k_cov(const float* __restrict__ fp) {
    int b  = blockIdx.z;
    int d0 = blockIdx.y * 16;
    int e0 = blockIdx.x * 16;
    int ty = threadIdx.y, tx = threadIdx.x;
    __shared__ float Ad[16][17];
    __shared__ float Ae[16][17];
    float md = g_mean[b * LAT + d0 + tx];
    float me = g_mean[b * LAT + e0 + tx];
    const float* base = fp + (size_t)b * NTRAJ * LAT;
    float acc = 0.f;
    for (int n0 = 0; n0 < NTRAJ; n0 += 16) {
        Ad[ty][tx] = base[(size_t)(n0 + ty) * LAT + d0 + tx] - md;
        Ae[ty][tx] = base[(size_t)(n0 + ty) * LAT + e0 + tx] - me;
        __syncthreads();
        #pragma unroll
        for (int k = 0; k < 16; k++)
            acc = fmaf(Ad[k][ty], Ae[k][tx], acc);
        __syncthreads();
    }
    g_cov[((size_t)(b * LAT + d0 + ty)) * LAT + e0 + tx] = acc;
}

__global__ void k_corr() {
    int i = blockIdx.x * blockDim.x + threadIdx.x;
    if (i >= BDIM * LAT * LAT) return;
    int e = i % LAT;
    int d = (i / LAT) % LAT;
    int b = i / (LAT * LAT);
    float c  = g_cov[i];
    float dd = g_cov[((size_t)(b * LAT + d)) * LAT + d];
    float de = g_cov[((size_t)(b * LAT + e)) * LAT + e];
    g_x[((size_t)(b * NROWS + NTRAJ + d)) * LAT + e] = c * rsqrtf(dd * de);
}

// ---------------- tf32 tensor-core GEMM ---------------------------------------
// C[M,N] = A[M,K] @ B[K,N], 128x128x16 block tile, 256 threads (8 warps),
// warp tile 64x32 (4x4 grid of m16n8k8 mma), double-buffered smem.
//
// G1 (IS_G1=true):  A = g_x + cf*g_k (fused), B = W1, epilogue tanh(.+b1) -> g_h
// G2 (IS_G1=false): A = g_h, B = W2, epilogue = RK4 bookkeeping (mode 0/1/2)
template<int KDIM, bool IS_G1>
__global__ __launch_bounds__(256, 2)
void k_mma(const float* __restrict__ B, const float* __restrict__ ts, int step,
           float cmul, const float* __restrict__ b1, int mode, float wgt,
           float* __restrict__ out) {
    constexpr int NDIM = IS_G1 ? HID : LAT;   // B row stride == total N
    constexpr int NIT  = KDIM / 16;

    __shared__ float As[2][128][20];
    __shared__ float Bs[2][16][136];

    const int m0 = blockIdx.y * 128;
    const int n0 = blockIdx.x * 128;
    const int tid  = threadIdx.x;
    const int lane = tid & 31;
    const int warp = tid >> 5;
    const int wm = warp & 1;        // 0..1  -> 64-row half
    const int wn = warp >> 1;       // 0..3  -> 32-col quarter
    const int r  = lane >> 2;       // groupID 0..7
    const int cq = lane & 3;        // thread-in-group 0..3

    const float dt = ts[step + 1] - ts[step];
    const float cf = cmul * dt;

    // global load mapping
    const int aRow = tid >> 2;          // 0..63 (+64 for l=1)
    const int aKq  = tid & 3;           // float4 index within 16-k tile
    const int bN   = (tid & 31) * 4;    // 0..124
    const int bK   = tid >> 5;          // 0..7  (+8 for l=1)

    const float* Ap = (IS_G1 ? g_x : g_h) + (size_t)(m0 + aRow) * KDIM + 4 * aKq;
    const float* Kp = g_k + (size_t)(m0 + aRow) * LAT + 4 * aKq;
    const float* Bp = B + (size_t)bK * NDIM + n0 + bN;

    float4 aR[2], bR[2];

    auto ldg = [&](int it) {
        #pragma unroll
        for (int l = 0; l < 2; l++) {
            float4 v = *(const float4*)(Ap + (size_t)l * 64 * KDIM + it * 16);
            if (IS_G1 && cf != 0.0f) {
                float4 kk = *(const float4*)(Kp + (size_t)l * 64 * LAT + it * 16);
                v.x = fmaf(cf, kk.x, v.x); v.y = fmaf(cf, kk.y, v.y);
                v.z = fmaf(cf, kk.z, v.z); v.w = fmaf(cf, kk.w, v.w);
            }
            aR[l] = v;
            bR[l] = *(const float4*)(Bp + (size_t)(it * 16 + l * 8) * NDIM);
        }
    };
    auto sts = [&](int buf) {
        #pragma unroll
        for (int l = 0; l < 2; l++) {
            As[buf][aRow + 64 * l][4 * aKq + 0] = to_tf32(aR[l].x);
            As[buf][aRow + 64 * l][4 * aKq + 1] = to_tf32(aR[l].y);
            As[buf][aRow + 64 * l][4 * aKq + 2] = to_tf32(aR[l].z);
            As[buf][aRow + 64 * l][4 * aKq + 3] = to_tf32(aR[l].w);
            float4 t;
            t.x = to_tf32(bR[l].x); t.y = to_tf32(bR[l].y);
            t.z = to_tf32(bR[l].z); t.w = to_tf32(bR[l].w);
            *(float4*)&Bs[buf][bK + 8 * l][bN] = t;
        }
    };

    float acc[4][4][4] = {};

    ldg(0);
    sts(0);
    __syncthreads();
    int cur = 0;

    #pragma unroll 1
    for (int it = 0; it < NIT; it++) {
        if (it + 1 < NIT) ldg(it + 1);

        #pragma unroll
        for (int ks = 0; ks < 2; ks++) {
            uint32_t af[4][4], bf[4][2];
            #pragma unroll
            for (int mt = 0; mt < 4; mt++) {
                int row = wm * 64 + mt * 16 + r;
                int col = ks * 8 + cq;
                af[mt][0] = __float_as_uint(As[cur][row][col]);
                af[mt][1] = __float_as_uint(As[cur][row + 8][col]);
                af[mt][2] = __float_as_uint(As[cur][row][col + 4]);
                af[mt][3] = __float_as_uint(As[cur][row + 8][col + 4]);
            }
            #pragma unroll
            for (int nt = 0; nt < 4; nt++) {
                int n = wn * 32 + nt * 8 + r;
                bf[nt][0] = __float_as_uint(Bs[cur][ks * 8 + cq][n]);
                bf[nt][1] = __float_as_uint(Bs[cur][ks * 8 + cq + 4][n]);
            }
            #pragma unroll
            for (int mt = 0; mt < 4; mt++)
                #pragma unroll
                for (int nt = 0; nt < 4; nt++)
                    mma_tf32(acc[mt][nt], af[mt], bf[nt]);
        }

        if (it + 1 < NIT) sts(cur ^ 1);
        __syncthreads();
        cur ^= 1;
    }

    // ---------------- epilogue ----------------
    if (IS_G1) {
        #pragma unroll
        for (int mt = 0; mt < 4; mt++) {
            int row0 = m0 + wm * 64 + mt * 16 + r;
            #pragma unroll
            for (int nt = 0; nt < 4; nt++) {
                int col = n0 + wn * 32 + nt * 8 + 2 * cq;
                float bx = __ldg(b1 + col), by = __ldg(b1 + col + 1);
                float2 v0, v1;
                v0.x = tanh_fast(acc[mt][nt][0] + bx);
                v0.y = tanh_fast(acc[mt][nt][1] + by);
                v1.x = tanh_fast(acc[mt][nt][2] + bx);
                v1.y = tanh_fast(acc[mt][nt][3] + by);
                *(float2*)(g_h + (size_t)row0 * HID + col) = v0;
                *(float2*)(g_h + (size_t)(row0 + 8) * HID + col) = v1;
            }
        }
    } else {
        float s6 = dt * (1.0f / 6.0f);
        #pragma unroll
        for (int mt = 0; mt < 4; mt++) {
            #pragma unroll
            for (int h = 0; h < 2; h++) {
                int row = m0 + wm * 64 + mt * 16 + r + 8 * h;
                int b = row / NROWS;
                int n = row % NROWS;
                #pragma unroll
                for (int nt = 0; nt < 4; nt++) {
                    int col = n0 + wn * 32 + nt * 8 + 2 * cq;
                    float v0 = acc[mt][nt][2 * h + 0];
                    float v1 = acc[mt][nt][2 * h + 1];
                    size_t idx = (size_t)row * LAT + col;
                    if (mode == 0) {
                        g_ksum[idx] = v0;   g_ksum[idx + 1] = v1;
                        g_k[idx]    = v0;   g_k[idx + 1]    = v1;
                    } else if (mode == 1) {
                        g_ksum[idx] += wgt * v0;  g_ksum[idx + 1] += wgt * v1;
                        g_k[idx]    = v0;         g_k[idx + 1]    = v1;
                    } else {
                        float x0 = g_x[idx]     + s6 * (g_ksum[idx]     + v0);
                        float x1 = g_x[idx + 1] + s6 * (g_ksum[idx + 1] + v1);
                        g_x[idx] = x0; g_x[idx + 1] = x1;
                        if (n < NTRAJ) {
                            size_t o = ((((size_t)b * NTRAJ) + n) * TSTEPS + (step + 1)) * LAT + col;
                            out[o] = x0; out[o + 1] = x1;
                        }
                    }
                }
            }
        }
    }
}

// ---------------- launch ------------------------------------------------------
extern "C" void kernel_launch(void* const* d_in, const int* in_sizes, int n_in,
                              void* d_out, int out_size) {
    const float* fp = (const float*)d_in[0];   // first_point (32,512,256)
    const float* ts = (const float*)d_in[1];   // time steps (10)
    const float* W1 = (const float*)d_in[2];   // (256,1024)
    const float* b1 = (const float*)d_in[3];   // (1024)
    const float* W2 = (const float*)d_in[4];   // (1024,256)
    float* out = (float*)d_out;                // (32,512,10,256)

    k_init<<<(BDIM * NTRAJ * LAT + 255) / 256, 256>>>(fp, out);
    k_mean<<<BDIM, LAT>>>(fp);
    k_cov<<<dim3(LAT / 16, LAT / 16, BDIM), dim3(16, 16)>>>(fp);
    k_corr<<<(BDIM * LAT * LAT + 255) / 256, 256>>>();

    dim3 g1(HID / 128, MTOT / 128);   // (8, 192)
    dim3 g2(LAT / 128, MTOT / 128);   // (2, 192)

    for (int s = 0; s < TSTEPS - 1; s++) {
        // eval 1: input x
        k_mma<LAT, true ><<<g1, 256>>>(W1, ts, s, 0.0f, b1, 0, 0.f, nullptr);
        k_mma<HID, false><<<g2, 256>>>(W2, ts, s, 0.0f, nullptr, 0, 1.0f, out);
        // eval 2: input x + 0.5*dt*k1
        k_mma<LAT, true ><<<g1, 256>>>(W1, ts, s, 0.5f, b1, 0, 0.f, nullptr);
        k_mma<HID, false><<<g2, 256>>>(W2, ts, s, 0.0f, nullptr, 1, 2.0f, out);
        // eval 3: input x + 0.5*dt*k2
        k_mma<LAT, true ><<<g1, 256>>>(W1, ts, s, 0.5f, b1, 0, 0.f, nullptr);
        k_mma<HID, false><<<g2, 256>>>(W2, ts, s, 0.0f, nullptr, 1, 2.0f, out);
        // eval 4: input x + dt*k3; finalize step
        k_mma<LAT, true ><<<g1, 256>>>(W1, ts, s, 1.0f, b1, 0, 0.f, nullptr);
        k_mma<HID, false><<<g2, 256>>>(W2, ts, s, 0.0f, nullptr, 2, 1.0f, out);
    }
}

// round 4
// speedup vs baseline: 3.9388x; 1.3094x over previous
#include <cuda_runtime.h>
#include <cuda_bf16.h>
#include <math.h>
#include <stdint.h>

// Problem constants
#define BDIM   32
#define NTRAJ  512
#define LAT    256
#define HID    1024
#define TSTEPS 10
#define NROWS  (NTRAJ + LAT)        // 768
#define MTOT   (BDIM * NROWS)       // 24576

// ---------------- scratch ----------------------------------------------------
__device__ __align__(16) float         g_x   [MTOT * LAT];   // committed state
__device__ __align__(16) float         g_xin [MTOT * LAT];   // next eval input
__device__ __align__(16) float         g_ksum[MTOT * LAT];   // weighted k accum
__device__ __align__(16) __nv_bfloat16 g_h   [MTOT * HID];   // hidden (bf16)
__device__ __align__(16) __nv_bfloat16 g_W2T [LAT * HID];    // W2^T [n=256][k=1024] bf16
__device__ float g_mean[BDIM * LAT];
__device__ float g_cov [BDIM * LAT * LAT];

// ---------------- helpers -----------------------------------------------------
__device__ __forceinline__ float tanh_fast(float x) {
    float y;
    asm("tanh.approx.f32 %0, %1;" : "=f"(y) : "f"(x));
    return y;
}

__device__ __forceinline__ void mma_tf32(float* d, const uint32_t* a, const uint32_t* b) {
    asm("mma.sync.aligned.m16n8k8.row.col.f32.tf32.tf32.f32 "
        "{%0,%1,%2,%3},{%4,%5,%6,%7},{%8,%9},{%0,%1,%2,%3};"
        : "+f"(d[0]), "+f"(d[1]), "+f"(d[2]), "+f"(d[3])
        : "r"(a[0]), "r"(a[1]), "r"(a[2]), "r"(a[3]), "r"(b[0]), "r"(b[1]));
}

__device__ __forceinline__ void mma_bf16(float* d, const uint32_t* a, const uint32_t* b) {
    asm("mma.sync.aligned.m16n8k16.row.col.f32.bf16.bf16.f32 "
        "{%0,%1,%2,%3},{%4,%5,%6,%7},{%8,%9},{%0,%1,%2,%3};"
        : "+f"(d[0]), "+f"(d[1]), "+f"(d[2]), "+f"(d[3])
        : "r"(a[0]), "r"(a[1]), "r"(a[2]), "r"(a[3]), "r"(b[0]), "r"(b[1]));
}

// ---------------- setup kernels ----------------------------------------------
__global__ void k_init(const float* __restrict__ fp, float* __restrict__ out) {
    int i = blockIdx.x * blockDim.x + threadIdx.x;
    if (i >= BDIM * NTRAJ * LAT) return;
    int c = i % LAT;
    int n = (i / LAT) % NTRAJ;
    int b = i / (LAT * NTRAJ);
    float v = fp[i];
    size_t idx = ((size_t)(b * NROWS + n)) * LAT + c;
    g_x[idx] = v;
    g_xin[idx] = v;
    out[((((size_t)b * NTRAJ) + n) * TSTEPS + 0) * LAT + c] = v;
}

__global__ void k_mean(const float* __restrict__ fp) {
    int b = blockIdx.x;
    int d = threadIdx.x;
    const float* p = fp + (size_t)b * NTRAJ * LAT + d;
    float s = 0.f;
    for (int n = 0; n < NTRAJ; n++) s += p[(size_t)n * LAT];
    g_mean[b * LAT + d] = s * (1.0f / NTRAJ);
}

__global__ void k_cov(const float* __restrict__ fp) {
    int b  = blockIdx.z;
    int d0 = blockIdx.y * 16;
    int e0 = blockIdx.x * 16;
    int ty = threadIdx.y, tx = threadIdx.x;
    __shared__ float Ad[16][17];
    __shared__ float Ae[16][17];
    float md = g_mean[b * LAT + d0 + tx];
    float me = g_mean[b * LAT + e0 + tx];
    const float* base = fp + (size_t)b * NTRAJ * LAT;
    float acc = 0.f;
    for (int n0 = 0; n0 < NTRAJ; n0 += 16) {
        Ad[ty][tx] = base[(size_t)(n0 + ty) * LAT + d0 + tx] - md;
        Ae[ty][tx] = base[(size_t)(n0 + ty) * LAT + e0 + tx] - me;
        __syncthreads();
        #pragma unroll
        for (int k = 0; k < 16; k++)
            acc = fmaf(Ad[k][ty], Ae[k][tx], acc);
        __syncthreads();
    }
    g_cov[((size_t)(b * LAT + d0 + ty)) * LAT + e0 + tx] = acc;
}

__global__ void k_corr() {
    int i = blockIdx.x * blockDim.x + threadIdx.x;
    if (i >= BDIM * LAT * LAT) return;
    int e = i % LAT;
    int d = (i / LAT) % LAT;
    int b = i / (LAT * LAT);
    float c  = g_cov[i];
    float dd = g_cov[((size_t)(b * LAT + d)) * LAT + d];
    float de = g_cov[((size_t)(b * LAT + e)) * LAT + e];
    float v = c * rsqrtf(dd * de);
    size_t idx = ((size_t)(b * NROWS + NTRAJ + d)) * LAT + e;
    g_x[idx] = v;
    g_xin[idx] = v;
}

__global__ void k_w2t(const float* __restrict__ W2) {
    int i = blockIdx.x * blockDim.x + threadIdx.x;
    if (i >= HID * LAT) return;
    int k = i / LAT, n = i % LAT;
    g_W2T[(size_t)n * HID + k] = __float2bfloat16(W2[i]);
}

// ---------------- GEMM1 (tf32): H = tanh(xin @ W1 + b1) -> g_h (bf16) --------
// M=24576, K=256, N=1024. 128x128x16 block, 8 warps, warp 64x32.
__global__ __launch_bounds__(256, 2)
void k_g1(const float* __restrict__ W1, const float* __restrict__ b1) {
    __shared__ float As[2][128][20];
    __shared__ float Bs[2][16][136];

    const int m0 = blockIdx.y * 128;
    const int n0 = blockIdx.x * 128;
    const int tid  = threadIdx.x;
    const int lane = tid & 31;
    const int warp = tid >> 5;
    const int wm = warp & 1;
    const int wn = warp >> 1;
    const int r  = lane >> 2;
    const int cq = lane & 3;

    const int aRow = tid >> 2;
    const int aKq  = tid & 3;
    const int bN   = (tid & 31) * 4;
    const int bK   = tid >> 5;

    const float* Ap = g_xin + (size_t)(m0 + aRow) * LAT + 4 * aKq;
    const float* Bp = W1 + (size_t)bK * HID + n0 + bN;

    float4 aR[2], bR[2];

    auto ldg = [&](int it) {
        #pragma unroll
        for (int l = 0; l < 2; l++) {
            aR[l] = *(const float4*)(Ap + (size_t)l * 64 * LAT + it * 16);
            bR[l] = *(const float4*)(Bp + (size_t)(it * 16 + l * 8) * HID);
        }
    };
    auto sts = [&](int buf) {
        #pragma unroll
        for (int l = 0; l < 2; l++) {
            As[buf][aRow + 64 * l][4 * aKq + 0] = aR[l].x;
            As[buf][aRow + 64 * l][4 * aKq + 1] = aR[l].y;
            As[buf][aRow + 64 * l][4 * aKq + 2] = aR[l].z;
            As[buf][aRow + 64 * l][4 * aKq + 3] = aR[l].w;
            *(float4*)&Bs[buf][bK + 8 * l][bN] = bR[l];
        }
    };

    float acc[4][4][4] = {};

    ldg(0);
    sts(0);
    __syncthreads();
    int cur = 0;

    #pragma unroll 1
    for (int it = 0; it < 16; it++) {
        if (it + 1 < 16) ldg(it + 1);

        #pragma unroll
        for (int ks = 0; ks < 2; ks++) {
            uint32_t af[4][4], bf[4][2];
            #pragma unroll
            for (int mt = 0; mt < 4; mt++) {
                int row = wm * 64 + mt * 16 + r;
                int col = ks * 8 + cq;
                af[mt][0] = __float_as_uint(As[cur][row][col]);
                af[mt][1] = __float_as_uint(As[cur][row + 8][col]);
                af[mt][2] = __float_as_uint(As[cur][row][col + 4]);
                af[mt][3] = __float_as_uint(As[cur][row + 8][col + 4]);
            }
            #pragma unroll
            for (int nt = 0; nt < 4; nt++) {
                int n = wn * 32 + nt * 8 + r;
                bf[nt][0] = __float_as_uint(Bs[cur][ks * 8 + cq][n]);
                bf[nt][1] = __float_as_uint(Bs[cur][ks * 8 + cq + 4][n]);
            }
            #pragma unroll
            for (int mt = 0; mt < 4; mt++)
                #pragma unroll
                for (int nt = 0; nt < 4; nt++)
                    mma_tf32(acc[mt][nt], af[mt], bf[nt]);
        }

        if (it + 1 < 16) sts(cur ^ 1);
        __syncthreads();
        cur ^= 1;
    }

    // epilogue: tanh(acc + b1) -> bf16 g_h (c0,c1 are adjacent cols -> bf16x2)
    #pragma unroll
    for (int mt = 0; mt < 4; mt++) {
        int row0 = m0 + wm * 64 + mt * 16 + r;
        #pragma unroll
        for (int nt = 0; nt < 4; nt++) {
            int col = n0 + wn * 32 + nt * 8 + 2 * cq;
            float bx = __ldg(b1 + col), by = __ldg(b1 + col + 1);
            float t0 = tanh_fast(acc[mt][nt][0] + bx);
            float t1 = tanh_fast(acc[mt][nt][1] + by);
            float t2 = tanh_fast(acc[mt][nt][2] + bx);
            float t3 = tanh_fast(acc[mt][nt][3] + by);
            uint32_t p0, p1;
            asm("cvt.rn.bf16x2.f32 %0, %1, %2;" : "=r"(p0) : "f"(t1), "f"(t0));
            asm("cvt.rn.bf16x2.f32 %0, %1, %2;" : "=r"(p1) : "f"(t3), "f"(t2));
            *(uint32_t*)((char*)g_h + ((size_t)row0 * HID + col) * 2) = p0;
            *(uint32_t*)((char*)g_h + ((size_t)(row0 + 8) * HID + col) * 2) = p1;
        }
    }
}

// ---------------- GEMM2 (bf16): Kv = h @ W2, fused RK4 epilogue ---------------
// M=24576, K=1024, N=256. 128x128x32 block, 8 warps, warp 64x32, m16n8k16.
// mode 0: ksum=v,  xin = x + cn*v
// mode 1: ksum+=2v, xin = x + cn*v
// mode 2: x += dt/6*(ksum+v); xin = x; write output slice step+1
__global__ __launch_bounds__(256, 2)
void k_g2(const float* __restrict__ ts, int step, int mode, float cnext,
          float* __restrict__ out) {
    // byte-addressed smem tiles: rows of 32 bf16 (64B) padded to 80B
    __shared__ char As[2][128 * 80];
    __shared__ char Bs[2][128 * 80];

    const int m0 = blockIdx.y * 128;
    const int n0 = blockIdx.x * 128;
    const int tid  = threadIdx.x;
    const int lane = tid & 31;
    const int warp = tid >> 5;
    const int wm = warp & 1;
    const int wn = warp >> 1;
    const int r  = lane >> 2;
    const int cq = lane & 3;

    // global loads: 8KB per tile per iter = 256 thr x 2 float4
    const int gRow = tid >> 2;       // 0..63 (+64 for l=1)
    const int gSeg = tid & 3;        // 16B segment within 64B row-chunk

    const char* Ap = (const char*)g_h + ((size_t)(m0 + gRow) * HID) * 2 + gSeg * 16;
    const char* Bp = (const char*)g_W2T + ((size_t)(n0 + gRow) * HID) * 2 + gSeg * 16;

    float4 aR[2], bR[2];

    auto ldg = [&](int it) {
        #pragma unroll
        for (int l = 0; l < 2; l++) {
            aR[l] = *(const float4*)(Ap + (size_t)(l * 64) * (HID * 2) + it * 64);
            bR[l] = *(const float4*)(Bp + (size_t)(l * 64) * (HID * 2) + it * 64);
        }
    };
    auto sts = [&](int buf) {
        #pragma unroll
        for (int l = 0; l < 2; l++) {
            *(float4*)(As[buf] + (gRow + 64 * l) * 80 + gSeg * 16) = aR[l];
            *(float4*)(Bs[buf] + (gRow + 64 * l) * 80 + gSeg * 16) = bR[l];
        }
    };

    float acc[4][4][4] = {};

    ldg(0);
    sts(0);
    __syncthreads();
    int cur = 0;

    #pragma unroll 1
    for (int it = 0; it < 32; it++) {
        if (it + 1 < 32) ldg(it + 1);

        #pragma unroll
        for (int ks = 0; ks < 2; ks++) {
            uint32_t af[4][4], bf[4][2];
            #pragma unroll
            for (int mt = 0; mt < 4; mt++) {
                const char* p = As[cur] + (wm * 64 + mt * 16 + r) * 80 + ks * 32 + cq * 4;
                af[mt][0] = *(const uint32_t*)(p);            // (r,   k 2cq..2cq+1)
                af[mt][1] = *(const uint32_t*)(p + 8 * 80);   // (r+8, ...)
                af[mt][2] = *(const uint32_t*)(p + 16);       // (r,   k +8)
                af[mt][3] = *(const uint32_t*)(p + 8 * 80 + 16);
            }
            #pragma unroll
            for (int nt = 0; nt < 4; nt++) {
                const char* p = Bs[cur] + (wn * 32 + nt * 8 + r) * 80 + ks * 32 + cq * 4;
                bf[nt][0] = *(const uint32_t*)(p);
                bf[nt][1] = *(const uint32_t*)(p + 16);
            }
            #pragma unroll
            for (int mt = 0; mt < 4; mt++)
                #pragma unroll
                for (int nt = 0; nt < 4; nt++)
                    mma_bf16(acc[mt][nt], af[mt], bf[nt]);
        }

        if (it + 1 < 32) sts(cur ^ 1);
        __syncthreads();
        cur ^= 1;
    }

    // epilogue: RK4 bookkeeping
    const float dt = ts[step + 1] - ts[step];
    const float cn = cnext * dt;
    const float s6 = dt * (1.0f / 6.0f);

    #pragma unroll
    for (int mt = 0; mt < 4; mt++) {
        #pragma unroll
        for (int h = 0; h < 2; h++) {
            int row = m0 + wm * 64 + mt * 16 + r + 8 * h;
            int b = row / NROWS;
            int n = row % NROWS;
            #pragma unroll
            for (int nt = 0; nt < 4; nt++) {
                int col = n0 + wn * 32 + nt * 8 + 2 * cq;
                float v0 = acc[mt][nt][2 * h + 0];
                float v1 = acc[mt][nt][2 * h + 1];
                size_t idx = (size_t)row * LAT + col;
                if (mode == 0) {
                    g_ksum[idx] = v0;  g_ksum[idx + 1] = v1;
                    float x0 = g_x[idx], x1 = g_x[idx + 1];
                    g_xin[idx]     = fmaf(cn, v0, x0);
                    g_xin[idx + 1] = fmaf(cn, v1, x1);
                } else if (mode == 1) {
                    g_ksum[idx]     += 2.f * v0;
                    g_ksum[idx + 1] += 2.f * v1;
                    float x0 = g_x[idx], x1 = g_x[idx + 1];
                    g_xin[idx]     = fmaf(cn, v0, x0);
                    g_xin[idx + 1] = fmaf(cn, v1, x1);
                } else {
                    float x0 = g_x[idx] + s6 * (g_ksum[idx] + v0);
                    float x1 = g_x[idx + 1] + s6 * (g_ksum[idx + 1] + v1);
                    g_x[idx] = x0;   g_x[idx + 1] = x1;
                    g_xin[idx] = x0; g_xin[idx + 1] = x1;
                    if (n < NTRAJ) {
                        size_t o = ((((size_t)b * NTRAJ) + n) * TSTEPS + (step + 1)) * LAT + col;
                        out[o] = x0; out[o + 1] = x1;
                    }
                }
            }
        }
    }
}

// ---------------- launch ------------------------------------------------------
extern "C" void kernel_launch(void* const* d_in, const int* in_sizes, int n_in,
                              void* d_out, int out_size) {
    const float* fp = (const float*)d_in[0];
    const float* ts = (const float*)d_in[1];
    const float* W1 = (const float*)d_in[2];
    const float* b1 = (const float*)d_in[3];
    const float* W2 = (const float*)d_in[4];
    float* out = (float*)d_out;

    k_init<<<(BDIM * NTRAJ * LAT + 255) / 256, 256>>>(fp, out);
    k_mean<<<BDIM, LAT>>>(fp);
    k_cov<<<dim3(LAT / 16, LAT / 16, BDIM), dim3(16, 16)>>>(fp);
    k_corr<<<(BDIM * LAT * LAT + 255) / 256, 256>>>();
    k_w2t<<<(HID * LAT + 255) / 256, 256>>>(W2);

    dim3 g1(HID / 128, MTOT / 128);   // (8, 192)
    dim3 g2(LAT / 128, MTOT / 128);   // (2, 192)

    for (int s = 0; s < TSTEPS - 1; s++) {
        // eval 1 -> k1: ksum = k1,  xin = x + 0.5*dt*k1
        k_g1<<<g1, 256>>>(W1, b1);
        k_g2<<<g2, 256>>>(ts, s, 0, 0.5f, out);
        // eval 2 -> k2: ksum += 2*k2, xin = x + 0.5*dt*k2
        k_g1<<<g1, 256>>>(W1, b1);
        k_g2<<<g2, 256>>>(ts, s, 1, 0.5f, out);
        // eval 3 -> k3: ksum += 2*k3, xin = x + dt*k3
        k_g1<<<g1, 256>>>(W1, b1);
        k_g2<<<g2, 256>>>(ts, s, 1, 1.0f, out);
        // eval 4 -> k4: x += dt/6*(ksum + k4); write slice; xin = x_new
        k_g1<<<g1, 256>>>(W1, b1);
        k_g2<<<g2, 256>>>(ts, s, 2, 0.0f, out);
    }
}

// round 5
// speedup vs baseline: 5.0643x; 1.2857x over previous
#include <cuda_runtime.h>
#include <cuda_fp16.h>
#include <math.h>
#include <stdint.h>

// Problem constants
#define BDIM   32
#define NTRAJ  512
#define LAT    256
#define HID    1024
#define TSTEPS 10
#define NROWS  (NTRAJ + LAT)        // 768
#define MTOT   (BDIM * NROWS)       // 24576

// ---------------- scratch ----------------------------------------------------
__device__ __align__(16) float  g_x   [MTOT * LAT];   // committed state (fp32)
__device__ __align__(16) float  g_ksum[MTOT * LAT];   // weighted k accum (fp32)
__device__ __align__(16) __half g_xin [MTOT * LAT];   // next eval input (fp16)
__device__ __align__(16) __half g_h   [MTOT * HID];   // hidden (fp16)
__device__ __align__(16) __half g_W1T [HID * LAT];    // W1^T [n=1024][k=256]
__device__ __align__(16) __half g_W2T [LAT * HID];    // W2^T [n=256][k=1024]
__device__ float g_mean[BDIM * LAT];
__device__ float g_cov [BDIM * LAT * LAT];

// ---------------- helpers -----------------------------------------------------
__device__ __forceinline__ float tanh_fast(float x) {
    float y;
    asm("tanh.approx.f32 %0, %1;" : "=f"(y) : "f"(x));
    return y;
}

__device__ __forceinline__ void mma_fp16(float* d, const uint32_t* a, const uint32_t* b) {
    asm("mma.sync.aligned.m16n8k16.row.col.f32.f16.f16.f32 "
        "{%0,%1,%2,%3},{%4,%5,%6,%7},{%8,%9},{%0,%1,%2,%3};"
        : "+f"(d[0]), "+f"(d[1]), "+f"(d[2]), "+f"(d[3])
        : "r"(a[0]), "r"(a[1]), "r"(a[2]), "r"(a[3]), "r"(b[0]), "r"(b[1]));
}

__device__ __forceinline__ uint32_t pack_h2(float lo, float hi) {
    uint32_t p;
    asm("cvt.rn.f16x2.f32 %0, %1, %2;" : "=r"(p) : "f"(hi), "f"(lo));
    return p;
}

// ---------------- setup kernels ----------------------------------------------
__global__ void k_init(const float* __restrict__ fp, float* __restrict__ out) {
    int i = blockIdx.x * blockDim.x + threadIdx.x;
    if (i >= BDIM * NTRAJ * LAT) return;
    int c = i % LAT;
    int n = (i / LAT) % NTRAJ;
    int b = i / (LAT * NTRAJ);
    float v = fp[i];
    size_t idx = ((size_t)(b * NROWS + n)) * LAT + c;
    g_x[idx] = v;
    g_xin[idx] = __float2half(v);
    out[((((size_t)b * NTRAJ) + n) * TSTEPS + 0) * LAT + c] = v;
}

__global__ void k_mean(const float* __restrict__ fp) {
    int b = blockIdx.x;
    int d = threadIdx.x;
    const float* p = fp + (size_t)b * NTRAJ * LAT + d;
    float s = 0.f;
    for (int n = 0; n < NTRAJ; n++) s += p[(size_t)n * LAT];
    g_mean[b * LAT + d] = s * (1.0f / NTRAJ);
}

__global__ void k_cov(const float* __restrict__ fp) {
    int b  = blockIdx.z;
    int d0 = blockIdx.y * 16;
    int e0 = blockIdx.x * 16;
    int ty = threadIdx.y, tx = threadIdx.x;
    __shared__ float Ad[16][17];
    __shared__ float Ae[16][17];
    float md = g_mean[b * LAT + d0 + tx];
    float me = g_mean[b * LAT + e0 + tx];
    const float* base = fp + (size_t)b * NTRAJ * LAT;
    float acc = 0.f;
    for (int n0 = 0; n0 < NTRAJ; n0 += 16) {
        Ad[ty][tx] = base[(size_t)(n0 + ty) * LAT + d0 + tx] - md;
        Ae[ty][tx] = base[(size_t)(n0 + ty) * LAT + e0 + tx] - me;
        __syncthreads();
        #pragma unroll
        for (int k = 0; k < 16; k++)
            acc = fmaf(Ad[k][ty], Ae[k][tx], acc);
        __syncthreads();
    }
    g_cov[((size_t)(b * LAT + d0 + ty)) * LAT + e0 + tx] = acc;
}

__global__ void k_corr() {
    int i = blockIdx.x * blockDim.x + threadIdx.x;
    if (i >= BDIM * LAT * LAT) return;
    int e = i % LAT;
    int d = (i / LAT) % LAT;
    int b = i / (LAT * LAT);
    float c  = g_cov[i];
    float dd = g_cov[((size_t)(b * LAT + d)) * LAT + d];
    float de = g_cov[((size_t)(b * LAT + e)) * LAT + e];
    float v = c * rsqrtf(dd * de);
    size_t idx = ((size_t)(b * NROWS + NTRAJ + d)) * LAT + e;
    g_x[idx] = v;
    g_xin[idx] = __float2half(v);
}

__global__ void k_w1t(const float* __restrict__ W1) {
    int i = blockIdx.x * blockDim.x + threadIdx.x;
    if (i >= LAT * HID) return;
    int k = i / HID, n = i % HID;
    g_W1T[(size_t)n * LAT + k] = __float2half(W1[i]);
}
__global__ void k_w2t(const float* __restrict__ W2) {
    int i = blockIdx.x * blockDim.x + threadIdx.x;
    if (i >= HID * LAT) return;
    int k = i / LAT, n = i % LAT;
    g_W2T[(size_t)n * HID + k] = __float2half(W2[i]);
}

// ---------------- fp16 GEMM (m16n8k16), 128x128x32 block, 8 warps ------------
// A [M,KDIM] fp16 row-major, B^T [N,KDIM] fp16 row-major (B col-major).
// warp tile 64x32 (4x4 m16n8k16). smem rows: 32 halfs (64B) padded to 80B.
//
// IS_G1: A = g_xin (K=256),  B = g_W1T, epilogue tanh(.+b1) -> g_h
// else : A = g_h   (K=1024), B = g_W2T, epilogue RK4 bookkeeping:
//   mode 0: ksum = v;   xin = x + cn*v
//   mode 1: ksum += 2v; xin = x + cn*v
//   mode 2: x += dt/6*(ksum+v); xin = x; write output slice step+1
template<int KDIM, bool IS_G1>
__global__ __launch_bounds__(256, 2)
void k_mm(const float* __restrict__ b1v, const float* __restrict__ ts, int step,
          int mode, float cnext, float* __restrict__ out) {
    constexpr int NIT = KDIM / 32;
    constexpr int ROWB = KDIM * 2;          // gmem row bytes

    __shared__ char As[2][128 * 80];
    __shared__ char Bs[2][128 * 80];

    const int m0 = blockIdx.y * 128;
    const int n0 = blockIdx.x * 128;
    const int tid  = threadIdx.x;
    const int lane = tid & 31;
    const int warp = tid >> 5;
    const int wm = warp & 1;
    const int wn = warp >> 1;
    const int r  = lane >> 2;
    const int cq = lane & 3;

    const int gRow = tid >> 2;       // 0..63 (+64)
    const int gSeg = tid & 3;        // 16B segment within 64B chunk-row

    const char* Ap = (const char*)(IS_G1 ? g_xin : g_h)
                   + (size_t)(m0 + gRow) * ROWB + gSeg * 16;
    const char* Bp = (const char*)(IS_G1 ? g_W1T : g_W2T)
                   + (size_t)(n0 + gRow) * ROWB + gSeg * 16;

    float4 aR[2], bR[2];

    auto ldg = [&](int it) {
        #pragma unroll
        for (int l = 0; l < 2; l++) {
            aR[l] = *(const float4*)(Ap + (size_t)(l * 64) * ROWB + it * 64);
            bR[l] = *(const float4*)(Bp + (size_t)(l * 64) * ROWB + it * 64);
        }
    };
    auto sts = [&](int buf) {
        #pragma unroll
        for (int l = 0; l < 2; l++) {
            *(float4*)(As[buf] + (gRow + 64 * l) * 80 + gSeg * 16) = aR[l];
            *(float4*)(Bs[buf] + (gRow + 64 * l) * 80 + gSeg * 16) = bR[l];
        }
    };

    float acc[4][4][4] = {};

    ldg(0);
    sts(0);
    __syncthreads();
    int cur = 0;

    #pragma unroll 1
    for (int it = 0; it < NIT; it++) {
        if (it + 1 < NIT) ldg(it + 1);

        #pragma unroll
        for (int ks = 0; ks < 2; ks++) {
            uint32_t af[4][4], bf[4][2];
            #pragma unroll
            for (int mt = 0; mt < 4; mt++) {
                const char* p = As[cur] + (wm * 64 + mt * 16 + r) * 80 + ks * 32 + cq * 4;
                af[mt][0] = *(const uint32_t*)(p);
                af[mt][1] = *(const uint32_t*)(p + 8 * 80);
                af[mt][2] = *(const uint32_t*)(p + 16);
                af[mt][3] = *(const uint32_t*)(p + 8 * 80 + 16);
            }
            #pragma unroll
            for (int nt = 0; nt < 4; nt++) {
                const char* p = Bs[cur] + (wn * 32 + nt * 8 + r) * 80 + ks * 32 + cq * 4;
                bf[nt][0] = *(const uint32_t*)(p);
                bf[nt][1] = *(const uint32_t*)(p + 16);
            }
            #pragma unroll
            for (int mt = 0; mt < 4; mt++)
                #pragma unroll
                for (int nt = 0; nt < 4; nt++)
                    mma_fp16(acc[mt][nt], af[mt], bf[nt]);
        }

        if (it + 1 < NIT) sts(cur ^ 1);
        __syncthreads();
        cur ^= 1;
    }

    // ---------------- epilogue ----------------
    if (IS_G1) {
        #pragma unroll
        for (int mt = 0; mt < 4; mt++) {
            int row0 = m0 + wm * 64 + mt * 16 + r;
            #pragma unroll
            for (int nt = 0; nt < 4; nt++) {
                int col = n0 + wn * 32 + nt * 8 + 2 * cq;
                float bx = __ldg(b1v + col), by = __ldg(b1v + col + 1);
                float t0 = tanh_fast(acc[mt][nt][0] + bx);
                float t1 = tanh_fast(acc[mt][nt][1] + by);
                float t2 = tanh_fast(acc[mt][nt][2] + bx);
                float t3 = tanh_fast(acc[mt][nt][3] + by);
                *(uint32_t*)((char*)g_h + ((size_t)row0 * HID + col) * 2)
                    = pack_h2(t0, t1);
                *(uint32_t*)((char*)g_h + ((size_t)(row0 + 8) * HID + col) * 2)
                    = pack_h2(t2, t3);
            }
        }
    } else {
        const float dt = ts[step + 1] - ts[step];
        const float cn = cnext * dt;
        const float s6 = dt * (1.0f / 6.0f);

        #pragma unroll
        for (int mt = 0; mt < 4; mt++) {
            #pragma unroll
            for (int h = 0; h < 2; h++) {
                int row = m0 + wm * 64 + mt * 16 + r + 8 * h;
                int b = row / NROWS;
                int n = row % NROWS;
                #pragma unroll
                for (int nt = 0; nt < 4; nt++) {
                    int col = n0 + wn * 32 + nt * 8 + 2 * cq;
                    float v0 = acc[mt][nt][2 * h + 0];
                    float v1 = acc[mt][nt][2 * h + 1];
                    size_t idx = (size_t)row * LAT + col;
                    if (mode == 0) {
                        g_ksum[idx] = v0;  g_ksum[idx + 1] = v1;
                        float xi0 = fmaf(cn, v0, g_x[idx]);
                        float xi1 = fmaf(cn, v1, g_x[idx + 1]);
                        *(uint32_t*)((char*)g_xin + idx * 2) = pack_h2(xi0, xi1);
                    } else if (mode == 1) {
                        g_ksum[idx]     += 2.f * v0;
                        g_ksum[idx + 1] += 2.f * v1;
                        float xi0 = fmaf(cn, v0, g_x[idx]);
                        float xi1 = fmaf(cn, v1, g_x[idx + 1]);
                        *(uint32_t*)((char*)g_xin + idx * 2) = pack_h2(xi0, xi1);
                    } else {
                        float x0 = g_x[idx] + s6 * (g_ksum[idx] + v0);
                        float x1 = g_x[idx + 1] + s6 * (g_ksum[idx + 1] + v1);
                        g_x[idx] = x0;   g_x[idx + 1] = x1;
                        *(uint32_t*)((char*)g_xin + idx * 2) = pack_h2(x0, x1);
                        if (n < NTRAJ) {
                            size_t o = ((((size_t)b * NTRAJ) + n) * TSTEPS
                                        + (step + 1)) * LAT + col;
                            out[o] = x0; out[o + 1] = x1;
                        }
                    }
                }
            }
        }
    }
}

// ---------------- launch ------------------------------------------------------
extern "C" void kernel_launch(void* const* d_in, const int* in_sizes, int n_in,
                              void* d_out, int out_size) {
    const float* fp = (const float*)d_in[0];
    const float* ts = (const float*)d_in[1];
    const float* W1 = (const float*)d_in[2];
    const float* b1 = (const float*)d_in[3];
    const float* W2 = (const float*)d_in[4];
    float* out = (float*)d_out;

    k_init<<<(BDIM * NTRAJ * LAT + 255) / 256, 256>>>(fp, out);
    k_mean<<<BDIM, LAT>>>(fp);
    k_cov<<<dim3(LAT / 16, LAT / 16, BDIM), dim3(16, 16)>>>(fp);
    k_corr<<<(BDIM * LAT * LAT + 255) / 256, 256>>>();
    k_w1t<<<(LAT * HID + 255) / 256, 256>>>(W1);
    k_w2t<<<(HID * LAT + 255) / 256, 256>>>(W2);

    dim3 g1(HID / 128, MTOT / 128);   // (8, 192)
    dim3 g2(LAT / 128, MTOT / 128);   // (2, 192)

    for (int s = 0; s < TSTEPS - 1; s++) {
        // eval 1 -> k1: ksum = k1,  xin = x + 0.5*dt*k1
        k_mm<LAT,  true ><<<g1, 256>>>(b1, ts, s, 0, 0.0f, nullptr);
        k_mm<HID,  false><<<g2, 256>>>(nullptr, ts, s, 0, 0.5f, out);
        // eval 2 -> k2: ksum += 2*k2, xin = x + 0.5*dt*k2
        k_mm<LAT,  true ><<<g1, 256>>>(b1, ts, s, 0, 0.0f, nullptr);
        k_mm<HID,  false><<<g2, 256>>>(nullptr, ts, s, 1, 0.5f, out);
        // eval 3 -> k3: ksum += 2*k3, xin = x + dt*k3
        k_mm<LAT,  true ><<<g1, 256>>>(b1, ts, s, 0, 0.0f, nullptr);
        k_mm<HID,  false><<<g2, 256>>>(nullptr, ts, s, 1, 1.0f, out);
        // eval 4 -> k4: x += dt/6*(ksum + k4); write slice; xin = x_new
        k_mm<LAT,  true ><<<g1, 256>>>(b1, ts, s, 0, 0.0f, nullptr);
        k_mm<HID,  false><<<g2, 256>>>(nullptr, ts, s, 2, 0.0f, out);
    }
}

// round 6
// speedup vs baseline: 5.2892x; 1.0444x over previous
#include <cuda_runtime.h>
#include <cuda_fp16.h>
#include <math.h>
#include <stdint.h>

// Problem constants
#define BDIM   32
#define NTRAJ  512
#define LAT    256
#define HID    1024
#define TSTEPS 10
#define NROWS  (NTRAJ + LAT)        // 768
#define MTOT   (BDIM * NROWS)       // 24576

// ---------------- scratch ----------------------------------------------------
__device__ __align__(16) float  g_x   [MTOT * LAT];   // committed state (fp32)
__device__ __align__(16) float  g_ksum[MTOT * LAT];   // weighted k accum (fp32)
__device__ __align__(16) __half g_xin [MTOT * LAT];   // next eval input (fp16)
__device__ __align__(16) __half g_h   [MTOT * HID];   // hidden (fp16)
__device__ __align__(16) __half g_W1T [HID * LAT];    // W1^T [n=1024][k=256]
__device__ __align__(16) __half g_W2T [LAT * HID];    // W2^T [n=256][k=1024]
__device__ float g_mean[BDIM * LAT];
__device__ float g_cov [BDIM * LAT * LAT];

// ---------------- helpers -----------------------------------------------------
__device__ __forceinline__ float tanh_fast(float x) {
    float y;
    asm("tanh.approx.f32 %0, %1;" : "=f"(y) : "f"(x));
    return y;
}

__device__ __forceinline__ void mma_fp16(float* d, const uint32_t* a,
                                         uint32_t b0, uint32_t b1) {
    asm("mma.sync.aligned.m16n8k16.row.col.f32.f16.f16.f32 "
        "{%0,%1,%2,%3},{%4,%5,%6,%7},{%8,%9},{%0,%1,%2,%3};"
        : "+f"(d[0]), "+f"(d[1]), "+f"(d[2]), "+f"(d[3])
        : "r"(a[0]), "r"(a[1]), "r"(a[2]), "r"(a[3]), "r"(b0), "r"(b1));
}

__device__ __forceinline__ void ldsm4(uint32_t* r, uint32_t addr) {
    asm volatile("ldmatrix.sync.aligned.m8n8.x4.shared.b16 {%0,%1,%2,%3}, [%4];"
                 : "=r"(r[0]), "=r"(r[1]), "=r"(r[2]), "=r"(r[3]) : "r"(addr));
}

__device__ __forceinline__ void cp16(uint32_t dst, const void* src) {
    asm volatile("cp.async.cg.shared.global [%0], [%1], 16;"
                 :: "r"(dst), "l"(src));
}
__device__ __forceinline__ void cp_commit() {
    asm volatile("cp.async.commit_group;" ::: "memory");
}
template<int N>
__device__ __forceinline__ void cp_wait() {
    asm volatile("cp.async.wait_group %0;" :: "n"(N) : "memory");
}

__device__ __forceinline__ uint32_t smem_u32(const void* p) {
    uint32_t a;
    asm("{ .reg .u64 t; cvta.to.shared.u64 t, %1; cvt.u32.u64 %0, t; }"
        : "=r"(a) : "l"(p));
    return a;
}

__device__ __forceinline__ uint32_t pack_h2(float lo, float hi) {
    uint32_t p;
    asm("cvt.rn.f16x2.f32 %0, %1, %2;" : "=r"(p) : "f"(hi), "f"(lo));
    return p;
}

// ---------------- setup kernels ----------------------------------------------
__global__ void k_init(const float* __restrict__ fp, float* __restrict__ out) {
    int i = blockIdx.x * blockDim.x + threadIdx.x;
    if (i >= BDIM * NTRAJ * LAT) return;
    int c = i % LAT;
    int n = (i / LAT) % NTRAJ;
    int b = i / (LAT * NTRAJ);
    float v = fp[i];
    size_t idx = ((size_t)(b * NROWS + n)) * LAT + c;
    g_x[idx] = v;
    g_xin[idx] = __float2half(v);
    out[((((size_t)b * NTRAJ) + n) * TSTEPS + 0) * LAT + c] = v;
}

__global__ void k_mean(const float* __restrict__ fp) {
    int b = blockIdx.x;
    int d = threadIdx.x;
    const float* p = fp + (size_t)b * NTRAJ * LAT + d;
    float s = 0.f;
    for (int n = 0; n < NTRAJ; n++) s += p[(size_t)n * LAT];
    g_mean[b * LAT + d] = s * (1.0f / NTRAJ);
}

__global__ void k_cov(const float* __restrict__ fp) {
    int b  = blockIdx.z;
    int d0 = blockIdx.y * 16;
    int e0 = blockIdx.x * 16;
    int ty = threadIdx.y, tx = threadIdx.x;
    __shared__ float Ad[16][17];
    __shared__ float Ae[16][17];
    float md = g_mean[b * LAT + d0 + tx];
    float me = g_mean[b * LAT + e0 + tx];
    const float* base = fp + (size_t)b * NTRAJ * LAT;
    float acc = 0.f;
    for (int n0 = 0; n0 < NTRAJ; n0 += 16) {
        Ad[ty][tx] = base[(size_t)(n0 + ty) * LAT + d0 + tx] - md;
        Ae[ty][tx] = base[(size_t)(n0 + ty) * LAT + e0 + tx] - me;
        __syncthreads();
        #pragma unroll
        for (int k = 0; k < 16; k++)
            acc = fmaf(Ad[k][ty], Ae[k][tx], acc);
        __syncthreads();
    }
    g_cov[((size_t)(b * LAT + d0 + ty)) * LAT + e0 + tx] = acc;
}

__global__ void k_corr() {
    int i = blockIdx.x * blockDim.x + threadIdx.x;
    if (i >= BDIM * LAT * LAT) return;
    int e = i % LAT;
    int d = (i / LAT) % LAT;
    int b = i / (LAT * LAT);
    float c  = g_cov[i];
    float dd = g_cov[((size_t)(b * LAT + d)) * LAT + d];
    float de = g_cov[((size_t)(b * LAT + e)) * LAT + e];
    float v = c * rsqrtf(dd * de);
    size_t idx = ((size_t)(b * NROWS + NTRAJ + d)) * LAT + e;
    g_x[idx] = v;
    g_xin[idx] = __float2half(v);
}

__global__ void k_w1t(const float* __restrict__ W1) {
    int i = blockIdx.x * blockDim.x + threadIdx.x;
    if (i >= LAT * HID) return;
    int k = i / HID, n = i % HID;
    g_W1T[(size_t)n * LAT + k] = __float2half(W1[i]);
}
__global__ void k_w2t(const float* __restrict__ W2) {
    int i = blockIdx.x * blockDim.x + threadIdx.x;
    if (i >= HID * LAT) return;
    int k = i / LAT, n = i % LAT;
    g_W2T[(size_t)n * HID + k] = __float2half(W2[i]);
}

// ---------------- fp16 GEMM: 64x64 tile, 128 thr, cp.async + ldmatrix --------
// A [M,KDIM] fp16 row-major; B^T [N,KDIM] fp16 row-major. Warp tile 64x16.
// smem per stage: A 64 rows x 80B, B 64 rows x 80B (32 halfs payload/row).
// 3-stage cp.async pipeline, 1 __syncthreads per iter.
//
// IS_G1: A=g_xin (K=256), B=g_W1T, epilogue tanh(.+b1) -> g_h
// else : A=g_h   (K=1024), B=g_W2T, epilogue RK4 bookkeeping (mode 0/1/2)
#define STG_BYTES 10240   // 2 * 64 * 80

template<int KDIM, bool IS_G1>
__global__ __launch_bounds__(128, 5)
void k_mm(const float* __restrict__ b1v, const float* __restrict__ ts, int step,
          int mode, float cnext, float* __restrict__ out) {
    constexpr int NIT  = KDIM / 32;
    constexpr int ROWB = KDIM * 2;

    __shared__ __align__(16) char sm[3 * STG_BYTES];
    const uint32_t smB = smem_u32(sm);

    const int m0 = blockIdx.y * 64;
    const int n0 = blockIdx.x * 64;
    const int tid  = threadIdx.x;
    const int lane = tid & 31;
    const int wn   = tid >> 5;          // warp -> 16-wide n slice
    const int r  = lane >> 2;
    const int cq = lane & 3;

    // ldmatrix per-lane address parts
    const int sub = lane >> 3;
    const int rowPart = ((sub & 1) * 8 + (lane & 7));
    const int colPart = (sub >> 1) * 16;

    // cp.async mapping: 2 A rows + 2 B rows per thread per stage
    const int cRow = tid >> 2;          // 0..31 (+32)
    const int cSeg = tid & 3;

    const char* Ag = (const char*)(IS_G1 ? g_xin : g_h)
                   + (size_t)(m0 + cRow) * ROWB + cSeg * 16;
    const char* Bg = (const char*)(IS_G1 ? g_W1T : g_W2T)
                   + (size_t)(n0 + cRow) * ROWB + cSeg * 16;
    const uint32_t aDst0 = smB + cRow * 80 + cSeg * 16;
    const uint32_t bDst0 = smB + 5120 + cRow * 80 + cSeg * 16;

    auto copyStage = [&](int it, int s) {
        uint32_t so = (uint32_t)s * STG_BYTES;
        #pragma unroll
        for (int l = 0; l < 2; l++)
            cp16(aDst0 + so + l * 32 * 80, Ag + (size_t)(l * 32) * ROWB + it * 64);
        #pragma unroll
        for (int l = 0; l < 2; l++)
            cp16(bDst0 + so + l * 32 * 80, Bg + (size_t)(l * 32) * ROWB + it * 64);
        cp_commit();
    };

    float acc[4][2][4] = {};

    copyStage(0, 0);
    copyStage(1, 1);

    #pragma unroll 2
    for (int it = 0; it < NIT; it++) {
        if (it + 1 < NIT) cp_wait<1>(); else cp_wait<0>();
        __syncthreads();
        if (it + 2 < NIT) copyStage(it + 2, (it + 2) % 3);

        const uint32_t aB = smB + (uint32_t)(it % 3) * STG_BYTES;
        const uint32_t bB = aB + 5120;

        #pragma unroll
        for (int ks = 0; ks < 2; ks++) {
            uint32_t bq[4];
            ldsm4(bq, bB + (wn * 16 + rowPart) * 80 + ks * 32 + colPart);
            #pragma unroll
            for (int mt = 0; mt < 4; mt++) {
                uint32_t af[4];
                ldsm4(af, aB + (mt * 16 + rowPart) * 80 + ks * 32 + colPart);
                mma_fp16(acc[mt][0], af, bq[0], bq[2]);
                mma_fp16(acc[mt][1], af, bq[1], bq[3]);
            }
        }
    }

    // ---------------- epilogue ----------------
    if (IS_G1) {
        #pragma unroll
        for (int mt = 0; mt < 4; mt++) {
            int row0 = m0 + mt * 16 + r;
            #pragma unroll
            for (int nt = 0; nt < 2; nt++) {
                int col = n0 + wn * 16 + nt * 8 + 2 * cq;
                float bx = __ldg(b1v + col), by = __ldg(b1v + col + 1);
                float t0 = tanh_fast(acc[mt][nt][0] + bx);
                float t1 = tanh_fast(acc[mt][nt][1] + by);
                float t2 = tanh_fast(acc[mt][nt][2] + bx);
                float t3 = tanh_fast(acc[mt][nt][3] + by);
                *(uint32_t*)((char*)g_h + ((size_t)row0 * HID + col) * 2)
                    = pack_h2(t0, t1);
                *(uint32_t*)((char*)g_h + ((size_t)(row0 + 8) * HID + col) * 2)
                    = pack_h2(t2, t3);
            }
        }
    } else {
        const float dt = ts[step + 1] - ts[step];
        const float cn = cnext * dt;
        const float s6 = dt * (1.0f / 6.0f);

        #pragma unroll
        for (int mt = 0; mt < 4; mt++) {
            #pragma unroll
            for (int h = 0; h < 2; h++) {
                int row = m0 + mt * 16 + r + 8 * h;
                int b = row / NROWS;
                int n = row % NROWS;
                #pragma unroll
                for (int nt = 0; nt < 2; nt++) {
                    int col = n0 + wn * 16 + nt * 8 + 2 * cq;
                    float v0 = acc[mt][nt][2 * h + 0];
                    float v1 = acc[mt][nt][2 * h + 1];
                    size_t idx = (size_t)row * LAT + col;
                    if (mode == 0) {
                        g_ksum[idx] = v0;  g_ksum[idx + 1] = v1;
                        float xi0 = fmaf(cn, v0, g_x[idx]);
                        float xi1 = fmaf(cn, v1, g_x[idx + 1]);
                        *(uint32_t*)((char*)g_xin + idx * 2) = pack_h2(xi0, xi1);
                    } else if (mode == 1) {
                        g_ksum[idx]     += 2.f * v0;
                        g_ksum[idx + 1] += 2.f * v1;
                        float xi0 = fmaf(cn, v0, g_x[idx]);
                        float xi1 = fmaf(cn, v1, g_x[idx + 1]);
                        *(uint32_t*)((char*)g_xin + idx * 2) = pack_h2(xi0, xi1);
                    } else {
                        float x0 = g_x[idx] + s6 * (g_ksum[idx] + v0);
                        float x1 = g_x[idx + 1] + s6 * (g_ksum[idx + 1] + v1);
                        g_x[idx] = x0;   g_x[idx + 1] = x1;
                        *(uint32_t*)((char*)g_xin + idx * 2) = pack_h2(x0, x1);
                        if (n < NTRAJ) {
                            size_t o = ((((size_t)b * NTRAJ) + n) * TSTEPS
                                        + (step + 1)) * LAT + col;
                            out[o] = x0; out[o + 1] = x1;
                        }
                    }
                }
            }
        }
    }
}

// ---------------- launch ------------------------------------------------------
extern "C" void kernel_launch(void* const* d_in, const int* in_sizes, int n_in,
                              void* d_out, int out_size) {
    const float* fp = (const float*)d_in[0];
    const float* ts = (const float*)d_in[1];
    const float* W1 = (const float*)d_in[2];
    const float* b1 = (const float*)d_in[3];
    const float* W2 = (const float*)d_in[4];
    float* out = (float*)d_out;

    k_init<<<(BDIM * NTRAJ * LAT + 255) / 256, 256>>>(fp, out);
    k_mean<<<BDIM, LAT>>>(fp);
    k_cov<<<dim3(LAT / 16, LAT / 16, BDIM), dim3(16, 16)>>>(fp);
    k_corr<<<(BDIM * LAT * LAT + 255) / 256, 256>>>();
    k_w1t<<<(LAT * HID + 255) / 256, 256>>>(W1);
    k_w2t<<<(HID * LAT + 255) / 256, 256>>>(W2);

    dim3 g1(HID / 64, MTOT / 64);   // (16, 384) = 6144 blocks
    dim3 g2(LAT / 64, MTOT / 64);   // (4, 384)  = 1536 blocks

    for (int s = 0; s < TSTEPS - 1; s++) {
        // eval 1 -> k1: ksum = k1,  xin = x + 0.5*dt*k1
        k_mm<LAT,  true ><<<g1, 128>>>(b1, ts, s, 0, 0.0f, nullptr);
        k_mm<HID,  false><<<g2, 128>>>(nullptr, ts, s, 0, 0.5f, out);
        // eval 2 -> k2: ksum += 2*k2, xin = x + 0.5*dt*k2
        k_mm<LAT,  true ><<<g1, 128>>>(b1, ts, s, 0, 0.0f, nullptr);
        k_mm<HID,  false><<<g2, 128>>>(nullptr, ts, s, 1, 0.5f, out);
        // eval 3 -> k3: ksum += 2*k3, xin = x + dt*k3
        k_mm<LAT,  true ><<<g1, 128>>>(b1, ts, s, 0, 0.0f, nullptr);
        k_mm<HID,  false><<<g2, 128>>>(nullptr, ts, s, 1, 1.0f, out);
        // eval 4 -> k4: x += dt/6*(ksum + k4); write slice; xin = x_new
        k_mm<LAT,  true ><<<g1, 128>>>(b1, ts, s, 0, 0.0f, nullptr);
        k_mm<HID,  false><<<g2, 128>>>(nullptr, ts, s, 2, 0.0f, out);
    }
}